// round 3
// baseline (speedup 1.0000x reference)
#include <cuda_runtime.h>
#include <cuda_bf16.h>
#include <math.h>

// Problem constants
#define BB 8
#define SS 512
#define DD 384
#define BSROWS (BB * SS)          // 4096
#define MAXR 128                  // max relevant s2 rows handled (expected ~8)
#define RC 16                     // rows per bilinear pass (register accumulators)
#define DCH 96                    // d-chunk per block
#define NCH (DD / DCH)            // 4
#define TH3 192                   // bilinear block size (= D/2, one e-pair per thread)

// -------- device scratch (no allocations allowed) --------
__device__ int   g_cnt;
__device__ int   g_src[MAXR];
__device__ int   g_dst[MAXR];
__device__ float g_w[MAXR];
__device__ float g_toff[DD];
__device__ float g_base[DD];
__device__ float g_tok[MAXR * DD];
__device__ float g_dep[MAXR * DD];
__device__ float g_u[MAXR * DD];

#define FMA2(acc, a, b) \
    asm("fma.rn.f32x2 %0, %1, %2, %0;" : "+l"(acc) : "l"(a), "l"(b))

// ============================================================================
// K1: one block, 512 threads. Builds everything data-dependent.
// ============================================================================
__global__ void prep_kernel(const int* __restrict__ tokens,
                            const int* __restrict__ heads,
                            const float* __restrict__ table,
                            const float* __restrict__ bc,
                            const float* __restrict__ Wr,
                            const float* __restrict__ br) {
    __shared__ float swred[SS];
    __shared__ int cnts[SS];
    const int tid = threadIdx.x;

    // ---- sum of Wr over S ----
    swred[tid] = Wr[tid];
    __syncthreads();
    for (int off = 256; off > 0; off >>= 1) {
        if (tid < off) swred[tid] += swred[tid + off];
        __syncthreads();
    }
    const float sw = swred[0];

    // ---- t_off / base ----
    if (tid < DD) {
        float t = tanhf(bc[tid]);
        g_toff[tid] = t;
        g_base[tid] = t * sw + br[0];
    }

    // ---- deterministic pair list via prefix scan (8 items/thread) ----
    const int base_i = tid * 8;
    int c = 0;
    #pragma unroll
    for (int k = 0; k < 8; k++) {
        int i = base_i + k;
        int h = heads[i];
        int b = i >> 9;
        if (heads[(b << 9) + h] == 0) c++;
    }
    cnts[tid] = c;
    __syncthreads();
    for (int off = 1; off < SS; off <<= 1) {
        int v = (tid >= off) ? cnts[tid - off] : 0;
        __syncthreads();
        cnts[tid] += v;
        __syncthreads();
    }
    const int start = cnts[tid] - c;
    const int total = cnts[SS - 1];
    if (tid == 0) g_cnt = (total > MAXR) ? MAXR : total;

    int pos = start;
    #pragma unroll
    for (int k = 0; k < 8; k++) {
        int i = base_i + k;
        int h = heads[i];
        int b = i >> 9;
        if (heads[(b << 9) + h] == 0) {
            if (pos < MAXR) {
                g_src[pos] = i;
                g_dst[pos] = (b << 9) + h;
                g_w[pos]   = Wr[i & (SS - 1)];
            }
            pos++;
        }
    }
    __syncthreads();

    // ---- zero u; gather tok/dep (zero-pad unused rows) ----
    const int cc = (total > MAXR) ? MAXR : total;
    for (int idx = tid; idx < MAXR * DD; idx += SS) {
        g_u[idx] = 0.f;
        int j = idx / DD;
        if (j < cc) {
            int d = idx - j * DD;
            float t = table[(size_t)tokens[g_src[j]] * DD + d];
            g_tok[idx] = t;
            g_dep[idx] = tanhf(t);
        } else {
            g_tok[idx] = 0.f;
            g_dep[idx] = 0.f;
        }
    }
}

// ============================================================================
// K2: out[row,:] = base if heads[row]==0 else 0   (writes every element)
// ============================================================================
__global__ void init_out_kernel(const int* __restrict__ heads,
                                float* __restrict__ out) {
    const int row = blockIdx.x;
    const int o = threadIdx.x;
    float v = (heads[row] == 0) ? g_base[o] : 0.f;
    out[(size_t)row * DD + o] = v;
}

// ============================================================================
// K3: stream Wc once. Block = (d-chunk, o). Thread owns e-pair (2*tid, 2*tid+1).
//     u[j,o] += sum_e dep[j,e] * sum_d tok[j,d] * Wc[o,d,e]
// ============================================================================
__global__ void __launch_bounds__(TH3, 4)
bilinear_kernel(const float* __restrict__ Wc) {
    const int o  = blockIdx.y;
    const int d0 = blockIdx.x * DCH;
    const int tid = threadIdx.x;
    const int cnt = g_cnt;
    if (cnt == 0) return;

    __shared__ __align__(16) unsigned long long tok_s[DCH][RC];  // {t,t} pairs
    __shared__ float red[RC][8];

    const int warp = tid >> 5;
    const int lane = tid & 31;

    const unsigned long long* __restrict__ Wp =
        reinterpret_cast<const unsigned long long*>(Wc) +
        ((size_t)o * DD + d0) * (DD / 2) + tid;

    const int npass = (cnt + RC - 1) / RC;
    for (int pass = 0; pass < npass; pass++) {
        const int jb = pass * RC;

        // fill smem: consecutive tid -> consecutive d (coalesced L2 reads)
        for (int idx = tid; idx < DCH * RC; idx += TH3) {
            int j = idx / DCH;
            int d = idx - j * DCH;
            float t = g_tok[(jb + j) * DD + d0 + d];
            unsigned long long p;
            asm("mov.b64 %0, {%1, %1};" : "=l"(p) : "f"(t));
            tok_s[d][j] = p;
        }
        __syncthreads();

        unsigned long long m[RC];
        #pragma unroll
        for (int j = 0; j < RC; j++) m[j] = 0ULL;

        #pragma unroll 4
        for (int d = 0; d < DCH; d++) {
            unsigned long long w = Wp[(size_t)d * (DD / 2)];
            const ulonglong2* tr = reinterpret_cast<const ulonglong2*>(&tok_s[d][0]);
            #pragma unroll
            for (int q = 0; q < RC / 2; q++) {
                ulonglong2 tp = tr[q];
                FMA2(m[2 * q],     tp.x, w);
                FMA2(m[2 * q + 1], tp.y, w);
            }
        }

        // apply dep at fixed e-pair, then block-reduce per row
        #pragma unroll
        for (int j = 0; j < RC; j++) {
            float mx, my;
            asm("mov.b64 {%0, %1}, %2;" : "=f"(mx), "=f"(my) : "l"(m[j]));
            const float* dp = &g_dep[(jb + j) * DD + 2 * tid];
            float val = mx * dp[0] + my * dp[1];
            #pragma unroll
            for (int off = 16; off > 0; off >>= 1)
                val += __shfl_down_sync(0xffffffffu, val, off);
            if (lane == 0) red[j][warp] = val;
        }
        __syncthreads();
        if (tid < RC) {
            float s = red[tid][0] + red[tid][1] + red[tid][2] +
                      red[tid][3] + red[tid][4] + red[tid][5];
            atomicAdd(&g_u[(jb + tid) * DD + o], s);
        }
        if (pass + 1 < npass) __syncthreads();
    }
}

// ============================================================================
// K4: out[dst_j,o] += (tanh(u[j,o] + bc[o]) - t_off[o]) * w[j]
// ============================================================================
__global__ void finalize_kernel(const float* __restrict__ bc,
                                float* __restrict__ out) {
    const int j = blockIdx.x;
    if (j >= g_cnt) return;
    const int o = threadIdx.x;
    float u = g_u[j * DD + o];
    float val = (tanhf(u + bc[o]) - g_toff[o]) * g_w[j];
    atomicAdd(&out[(size_t)g_dst[j] * DD + o], val);
}

// ============================================================================
// launch
// ============================================================================
extern "C" void kernel_launch(void* const* d_in, const int* in_sizes, int n_in,
                              void* d_out, int out_size) {
    const int*   tokens = (const int*)d_in[0];
    // d_in[1] = dep_types: unused (discarded in reference)
    const int*   heads  = (const int*)d_in[2];
    const float* table  = (const float*)d_in[3];
    const float* Wc     = (const float*)d_in[4];
    const float* bc     = (const float*)d_in[5];
    const float* Wr     = (const float*)d_in[6];
    const float* br     = (const float*)d_in[7];
    float* out = (float*)d_out;

    prep_kernel<<<1, SS>>>(tokens, heads, table, bc, Wr, br);
    init_out_kernel<<<BSROWS, DD>>>(heads, out);
    dim3 g3(NCH, DD);
    bilinear_kernel<<<g3, TH3>>>(Wc);
    finalize_kernel<<<MAXR, DD>>>(bc, out);
}

// round 5
// speedup vs baseline: 1.4196x; 1.4196x over previous
#include <cuda_runtime.h>
#include <cuda_bf16.h>
#include <math.h>

// Problem constants
#define BB 8
#define SS 512
#define DD 384
#define BSROWS (BB * SS)          // 4096
#define MAXR 128                  // cap on relevant s2 rows (expected ~8)
#define DCH 96                    // d rows per block
#define NCH (DD / DCH)            // 4
#define TH 384                    // bilinear block size
#define NWARP (TH / 32)           // 12

typedef unsigned long long ull;

// -------- device scratch (no allocations allowed) --------
__device__ int   g_cnt;
__device__ int   g_src[MAXR];
__device__ int   g_dst[MAXR];
__device__ float g_w[MAXR];
__device__ float g_toff[DD];
__device__ float g_base[DD];
__device__ float g_tok[MAXR * DD];
__device__ float g_dep[MAXR * DD];
__device__ float g_u[MAXR * DD];

#define FMA2(acc, a, b) \
    asm("fma.rn.f32x2 %0, %1, %2, %0;" : "+l"(acc) : "l"(a), "l"(b))
#define DUP(p, f) \
    asm("mov.b64 %0, {%1, %1};" : "=l"(p) : "f"(f))
#define PACK2(p, a, b) \
    asm("mov.b64 %0, {%1, %2};" : "=l"(p) : "f"(a), "f"(b))

// ============================================================================
// K1: one block, 512 threads. Builds everything data-dependent.
// ============================================================================
__global__ void prep_kernel(const int* __restrict__ tokens,
                            const int* __restrict__ heads,
                            const float* __restrict__ table,
                            const float* __restrict__ bc,
                            const float* __restrict__ Wr,
                            const float* __restrict__ br) {
    __shared__ float swred[SS];
    __shared__ int cnts[SS];
    const int tid = threadIdx.x;

    // ---- sum of Wr over S ----
    swred[tid] = Wr[tid];
    __syncthreads();
    for (int off = 256; off > 0; off >>= 1) {
        if (tid < off) swred[tid] += swred[tid + off];
        __syncthreads();
    }
    const float sw = swred[0];

    // ---- t_off / base ----
    if (tid < DD) {
        float t = tanhf(bc[tid]);
        g_toff[tid] = t;
        g_base[tid] = t * sw + br[0];
    }

    // ---- deterministic pair list via prefix scan (8 items/thread) ----
    const int base_i = tid * 8;
    int c = 0;
    #pragma unroll
    for (int k = 0; k < 8; k++) {
        int i = base_i + k;
        int h = heads[i];
        int b = i >> 9;
        if (heads[(b << 9) + h] == 0) c++;
    }
    cnts[tid] = c;
    __syncthreads();
    for (int off = 1; off < SS; off <<= 1) {
        int v = (tid >= off) ? cnts[tid - off] : 0;
        __syncthreads();
        cnts[tid] += v;
        __syncthreads();
    }
    const int start = cnts[tid] - c;
    const int total = cnts[SS - 1];
    if (tid == 0) g_cnt = (total > MAXR) ? MAXR : total;

    int pos = start;
    #pragma unroll
    for (int k = 0; k < 8; k++) {
        int i = base_i + k;
        int h = heads[i];
        int b = i >> 9;
        if (heads[(b << 9) + h] == 0) {
            if (pos < MAXR) {
                g_src[pos] = i;
                g_dst[pos] = (b << 9) + h;
                g_w[pos]   = Wr[i & (SS - 1)];
            }
            pos++;
        }
    }
    __syncthreads();

    // ---- zero u; gather tok/dep (zero-pad unused rows) ----
    const int cc = (total > MAXR) ? MAXR : total;
    for (int idx = tid; idx < MAXR * DD; idx += SS) {
        g_u[idx] = 0.f;
        int j = idx / DD;
        if (j < cc) {
            int d = idx - j * DD;
            float t = table[(size_t)tokens[g_src[j]] * DD + d];
            g_tok[idx] = t;
            g_dep[idx] = tanhf(t);
        } else {
            g_tok[idx] = 0.f;
            g_dep[idx] = 0.f;
        }
    }
}

// ============================================================================
// Bilinear body: u[jb+j][o] += sum_{d,e} tok[j,d] * Wc[o,d,e] * dep[j,e]
//   JP = j-pairs processed (rows R = 2*JP), EV = e floats per thread (4 or 2)
//   Block = 384 threads = (DD/EV e-threads) x (d-phases). Grid = (NCH, DD).
//   tok j-pairs live in smem ({tok[j0,d],tok[j1,d]} packed); W value is
//   register-duplicated -> only JP/2 LDS.128 per (thread, d).
// ============================================================================
template<int JP, int EV>
__device__ __forceinline__ void bilinear_body(const float* __restrict__ Wc,
                                              int jb) {
    constexpr int R   = 2 * JP;
    constexpr int ETH = DD / EV;        // e-threads per d-phase
    constexpr int DPH = TH / ETH;       // d-phases
    constexpr int KIT = DCH / DPH;      // d iterations per thread

    const int o   = blockIdx.y;
    const int d0  = blockIdx.x * DCH;
    const int tid = threadIdx.x;
    const int et  = tid % ETH;
    const int dph = tid / ETH;

    __shared__ __align__(16) ull tok_s[DCH][JP];
    __shared__ float red[R][NWARP];

    // fill tok j-pairs (coalesced enough; tiny)
    for (int idx = tid; idx < DCH * JP; idx += TH) {
        int d = idx / JP, q = idx - d * JP;
        float a = g_tok[(jb + 2 * q)     * DD + d0 + d];
        float b = g_tok[(jb + 2 * q + 1) * DD + d0 + d];
        ull p; PACK2(p, a, b);
        tok_s[d][q] = p;
    }
    __syncthreads();

    ull m[JP][EV];
    #pragma unroll
    for (int q = 0; q < JP; q++)
        #pragma unroll
        for (int c = 0; c < EV; c++) m[q][c] = 0ULL;

    const float* Wbase = Wc + ((size_t)o * DD + d0) * DD;

    if constexpr (EV == 4) {
        const float4* __restrict__ Wp = reinterpret_cast<const float4*>(Wbase) + et;
        const int rs = DD / 4;  // float4 per d row
        float4 w0 = Wp[(size_t)dph * rs];
        float4 w1 = (KIT > 1) ? Wp[(size_t)(dph + DPH) * rs] : w0;
        #pragma unroll
        for (int k = 0; k < KIT; k++) {
            float4 wn = w0;
            if (k + 2 < KIT) wn = Wp[(size_t)(dph + DPH * (k + 2)) * rs];
            const int d = dph + DPH * k;
            ull wd0, wd1, wd2, wd3;
            DUP(wd0, w0.x); DUP(wd1, w0.y); DUP(wd2, w0.z); DUP(wd3, w0.w);
            #pragma unroll
            for (int q = 0; q < JP; q++) {
                ull tp = tok_s[d][q];
                FMA2(m[q][0], tp, wd0);
                FMA2(m[q][1], tp, wd1);
                FMA2(m[q][2], tp, wd2);
                FMA2(m[q][3], tp, wd3);
            }
            w0 = w1; w1 = wn;
        }
    } else {
        const float2* __restrict__ Wp = reinterpret_cast<const float2*>(Wbase) + et;
        const int rs = DD / 2;
        float2 w0 = Wp[(size_t)dph * rs];
        float2 w1 = (KIT > 1) ? Wp[(size_t)(dph + DPH) * rs] : w0;
        #pragma unroll
        for (int k = 0; k < KIT; k++) {
            float2 wn = w0;
            if (k + 2 < KIT) wn = Wp[(size_t)(dph + DPH * (k + 2)) * rs];
            const int d = dph + DPH * k;
            ull wd0, wd1;
            DUP(wd0, w0.x); DUP(wd1, w0.y);
            #pragma unroll
            for (int q = 0; q < JP; q++) {
                ull tp = tok_s[d][q];
                FMA2(m[q][0], tp, wd0);
                FMA2(m[q][1], tp, wd1);
            }
            w0 = w1; w1 = wn;
        }
    }

    // apply dep at this thread's e-columns, accumulate per row
    float s[R];
    #pragma unroll
    for (int r = 0; r < R; r++) s[r] = 0.f;
    #pragma unroll
    for (int q = 0; q < JP; q++) {
        #pragma unroll
        for (int c = 0; c < EV; c++) {
            float mx, my;
            asm("mov.b64 {%0, %1}, %2;" : "=f"(mx), "=f"(my) : "l"(m[q][c]));
            int e = EV * et + c;
            s[2 * q]     += mx * g_dep[(jb + 2 * q)     * DD + e];
            s[2 * q + 1] += my * g_dep[(jb + 2 * q + 1) * DD + e];
        }
    }

    const int lane = tid & 31;
    const int warp = tid >> 5;
    #pragma unroll
    for (int r = 0; r < R; r++) {
        float v = s[r];
        #pragma unroll
        for (int off = 16; off > 0; off >>= 1)
            v += __shfl_down_sync(0xffffffffu, v, off);
        if (lane == 0) red[r][warp] = v;
    }
    __syncthreads();
    if (tid < R) {
        float acc = 0.f;
        #pragma unroll
        for (int wz = 0; wz < NWARP; wz++) acc += red[tid][wz];
        atomicAdd(&g_u[(jb + tid) * DD + o], acc);
    }
    __syncthreads();
}

// Handles cnt in [1,8] in one pass; cnt > 16 via multi-pass reread (rare).
__global__ void __launch_bounds__(TH, 2)
bilinear_r8(const float* __restrict__ Wc) {
    const int cnt = g_cnt;
    if (cnt == 0 || (cnt > 8 && cnt <= 16)) return;
    const int npass = (cnt + 7) / 8;
    for (int p = 0; p < npass; p++)
        bilinear_body<4, 4>(Wc, p * 8);
}

// Handles cnt in (8,16] in one pass.
__global__ void __launch_bounds__(TH, 2)
bilinear_r16(const float* __restrict__ Wc) {
    const int cnt = g_cnt;
    if (cnt <= 8 || cnt > 16) return;
    bilinear_body<8, 2>(Wc, 0);
}

// ============================================================================
// K4 (fused init+finalize): full output write.
//   out[row,o] = (heads[row]==0 ? base[o] : 0)
//              + sum_{j: dst[j]==row} (tanh(u[j,o]+bc[o]) - toff[o]) * w[j]
// ============================================================================
__global__ void finalize_kernel(const int* __restrict__ heads,
                                const float* __restrict__ bc,
                                float* __restrict__ out) {
    const int row = blockIdx.x;
    const int o = threadIdx.x;
    const int h0 = heads[row];
    float v = (h0 == 0) ? g_base[o] : 0.f;
    const int cnt = g_cnt;
    for (int j = 0; j < cnt; j++) {
        if (g_dst[j] == row) {
            float u = g_u[j * DD + o];
            v += (tanhf(u + bc[o]) - g_toff[o]) * g_w[j];
        }
    }
    out[(size_t)row * DD + o] = v;
}

// ============================================================================
// launch
// ============================================================================
extern "C" void kernel_launch(void* const* d_in, const int* in_sizes, int n_in,
                              void* d_out, int out_size) {
    const int*   tokens = (const int*)d_in[0];
    // d_in[1] = dep_types: unused (discarded in reference)
    const int*   heads  = (const int*)d_in[2];
    const float* table  = (const float*)d_in[3];
    const float* Wc     = (const float*)d_in[4];
    const float* bc     = (const float*)d_in[5];
    const float* Wr     = (const float*)d_in[6];
    const float* br     = (const float*)d_in[7];
    float* out = (float*)d_out;

    prep_kernel<<<1, SS>>>(tokens, heads, table, bc, Wr, br);
    dim3 g3(NCH, DD);
    bilinear_r8<<<g3, TH>>>(Wc);
    bilinear_r16<<<g3, TH>>>(Wc);
    finalize_kernel<<<BSROWS, DD>>>(heads, bc, out);
}

// round 6
// speedup vs baseline: 1.7635x; 1.2422x over previous
#include <cuda_runtime.h>
#include <cuda_bf16.h>
#include <math.h>

// Problem constants
#define BB 8
#define SS 512
#define DD 384
#define BSROWS (BB * SS)          // 4096
#define MAXR 128                  // cap on relevant s2 rows (expected ~8)
#define DCH 96                    // d rows per block
#define NCH (DD / DCH)            // 4
#define TH 384                    // bilinear block size
#define NWARP (TH / 32)           // 12

typedef unsigned long long ull;

// -------- device scratch (no allocations allowed) --------
__device__ int   g_cnt;
__device__ int   g_src[MAXR];
__device__ int   g_dst[MAXR];
__device__ float g_w[MAXR];
__device__ __align__(16) float g_toff[DD];
__device__ __align__(16) float g_base[DD];
__device__ __align__(16) float g_tok[MAXR * DD];
__device__ __align__(16) float g_dep[MAXR * DD];
__device__ __align__(16) float g_u[MAXR * DD];

#define FMA2(acc, a, b) \
    asm("fma.rn.f32x2 %0, %1, %2, %0;" : "+l"(acc) : "l"(a), "l"(b))
#define DUP(p, f) \
    asm("mov.b64 %0, {%1, %1};" : "=l"(p) : "f"(f))
#define PACK2(p, a, b) \
    asm("mov.b64 %0, {%1, %2};" : "=l"(p) : "f"(a), "f"(b))

// ============================================================================
// K1a: one block, 512 threads. Sequential scan part only.
// ============================================================================
__global__ void prep_scan_kernel(const int* __restrict__ heads,
                                 const float* __restrict__ bc,
                                 const float* __restrict__ Wr,
                                 const float* __restrict__ br) {
    __shared__ float swred[SS];
    __shared__ int cnts[SS];
    const int tid = threadIdx.x;

    // ---- sum of Wr over S ----
    swred[tid] = Wr[tid];
    __syncthreads();
    for (int off = 256; off > 0; off >>= 1) {
        if (tid < off) swred[tid] += swred[tid + off];
        __syncthreads();
    }
    const float sw = swred[0];

    // ---- t_off / base ----
    if (tid < DD) {
        float t = tanhf(bc[tid]);
        g_toff[tid] = t;
        g_base[tid] = t * sw + br[0];
    }

    // ---- deterministic pair list via prefix scan (8 items/thread) ----
    const int base_i = tid * 8;
    int c = 0;
    #pragma unroll
    for (int k = 0; k < 8; k++) {
        int i = base_i + k;
        int h = heads[i];
        int b = i >> 9;
        if (heads[(b << 9) + h] == 0) c++;
    }
    cnts[tid] = c;
    __syncthreads();
    for (int off = 1; off < SS; off <<= 1) {
        int v = (tid >= off) ? cnts[tid - off] : 0;
        __syncthreads();
        cnts[tid] += v;
        __syncthreads();
    }
    const int start = cnts[tid] - c;
    const int total = cnts[SS - 1];
    if (tid == 0) g_cnt = (total > MAXR) ? MAXR : total;

    int pos = start;
    #pragma unroll
    for (int k = 0; k < 8; k++) {
        int i = base_i + k;
        int h = heads[i];
        int b = i >> 9;
        if (heads[(b << 9) + h] == 0) {
            if (pos < MAXR) {
                g_src[pos] = i;
                g_dst[pos] = (b << 9) + h;
                g_w[pos]   = Wr[i & (SS - 1)];
            }
            pos++;
        }
    }
}

// ============================================================================
// K1b: parallel gather + zero. grid 192 x 256 over MAXR*DD elements.
// ============================================================================
__global__ void gather_kernel(const int* __restrict__ tokens,
                              const float* __restrict__ table) {
    const int idx = blockIdx.x * blockDim.x + threadIdx.x;  // < MAXR*DD
    g_u[idx] = 0.f;
    const int j = idx / DD;
    const int d = idx - j * DD;
    float t = 0.f;
    if (j < g_cnt) t = table[(size_t)tokens[g_src[j]] * DD + d];
    g_tok[idx] = t;
    g_dep[idx] = tanhf(t);   // tanh(0)=0 for padded rows
}

// ============================================================================
// Bilinear body: u[jb+j][o] += sum_{d,e} tok[j,d] * Wc[o,d,e] * dep[j,e]
//   JP = j-pairs (rows R = 2*JP), EV = e floats per thread.
//   tok j-pairs in smem ({tok[j0,d],tok[j1,d]} packed); W register-duplicated.
// ============================================================================
template<int JP, int EV>
__device__ __forceinline__ void bilinear_body(const float* __restrict__ Wc,
                                              int jb) {
    constexpr int R   = 2 * JP;
    constexpr int ETH = DD / EV;        // e-threads per d-phase
    constexpr int DPH = TH / ETH;       // d-phases
    constexpr int KIT = DCH / DPH;      // d iterations per thread

    const int o   = blockIdx.y;
    const int d0  = blockIdx.x * DCH;
    const int tid = threadIdx.x;
    const int et  = tid % ETH;
    const int dph = tid / ETH;

    __shared__ __align__(16) ull tok_s[DCH][JP];
    __shared__ float red[R][NWARP];

    for (int idx = tid; idx < DCH * JP; idx += TH) {
        int d = idx / JP, q = idx - d * JP;
        float a = g_tok[(jb + 2 * q)     * DD + d0 + d];
        float b = g_tok[(jb + 2 * q + 1) * DD + d0 + d];
        ull p; PACK2(p, a, b);
        tok_s[d][q] = p;
    }
    __syncthreads();

    ull m[JP][EV];
    #pragma unroll
    for (int q = 0; q < JP; q++)
        #pragma unroll
        for (int c = 0; c < EV; c++) m[q][c] = 0ULL;

    const float* Wbase = Wc + ((size_t)o * DD + d0) * DD;

    if constexpr (EV == 4) {
        const float4* __restrict__ Wp = reinterpret_cast<const float4*>(Wbase) + et;
        const int rs = DD / 4;
        float4 w0 = __ldcs(&Wp[(size_t)dph * rs]);
        float4 w1 = (KIT > 1) ? __ldcs(&Wp[(size_t)(dph + DPH) * rs]) : w0;
        #pragma unroll
        for (int k = 0; k < KIT; k++) {
            float4 wn = w0;
            if (k + 2 < KIT) wn = __ldcs(&Wp[(size_t)(dph + DPH * (k + 2)) * rs]);
            const int d = dph + DPH * k;
            ull wd0, wd1, wd2, wd3;
            DUP(wd0, w0.x); DUP(wd1, w0.y); DUP(wd2, w0.z); DUP(wd3, w0.w);
            #pragma unroll
            for (int q = 0; q < JP; q++) {
                ull tp = tok_s[d][q];
                FMA2(m[q][0], tp, wd0);
                FMA2(m[q][1], tp, wd1);
                FMA2(m[q][2], tp, wd2);
                FMA2(m[q][3], tp, wd3);
            }
            w0 = w1; w1 = wn;
        }
    } else {
        const float2* __restrict__ Wp = reinterpret_cast<const float2*>(Wbase) + et;
        const int rs = DD / 2;
        float2 w0 = __ldcs(&Wp[(size_t)dph * rs]);
        float2 w1 = (KIT > 1) ? __ldcs(&Wp[(size_t)(dph + DPH) * rs]) : w0;
        #pragma unroll
        for (int k = 0; k < KIT; k++) {
            float2 wn = w0;
            if (k + 2 < KIT) wn = __ldcs(&Wp[(size_t)(dph + DPH * (k + 2)) * rs]);
            const int d = dph + DPH * k;
            ull wd0, wd1;
            DUP(wd0, w0.x); DUP(wd1, w0.y);
            #pragma unroll
            for (int q = 0; q < JP; q++) {
                ull tp = tok_s[d][q];
                FMA2(m[q][0], tp, wd0);
                FMA2(m[q][1], tp, wd1);
            }
            w0 = w1; w1 = wn;
        }
    }

    // apply dep at this thread's e-columns, accumulate per row
    float s[R];
    #pragma unroll
    for (int r = 0; r < R; r++) s[r] = 0.f;
    #pragma unroll
    for (int q = 0; q < JP; q++) {
        #pragma unroll
        for (int c = 0; c < EV; c++) {
            float mx, my;
            asm("mov.b64 {%0, %1}, %2;" : "=f"(mx), "=f"(my) : "l"(m[q][c]));
            int e = EV * et + c;
            s[2 * q]     += mx * g_dep[(jb + 2 * q)     * DD + e];
            s[2 * q + 1] += my * g_dep[(jb + 2 * q + 1) * DD + e];
        }
    }

    const int lane = tid & 31;
    const int warp = tid >> 5;
    #pragma unroll
    for (int r = 0; r < R; r++) {
        float v = s[r];
        #pragma unroll
        for (int off = 16; off > 0; off >>= 1)
            v += __shfl_down_sync(0xffffffffu, v, off);
        if (lane == 0) red[r][warp] = v;
    }
    __syncthreads();
    if (tid < R) {
        float acc = 0.f;
        #pragma unroll
        for (int wz = 0; wz < NWARP; wz++) acc += red[tid][wz];
        atomicAdd(&g_u[(jb + tid) * DD + o], acc);
    }
    __syncthreads();
}

// Handles cnt in [1,8] in one pass; cnt > 16 via multi-pass reread (rare).
__global__ void __launch_bounds__(TH, 2)
bilinear_r8(const float* __restrict__ Wc) {
    const int cnt = g_cnt;
    if (cnt == 0 || (cnt > 8 && cnt <= 16)) return;
    const int npass = (cnt + 7) / 8;
    for (int p = 0; p < npass; p++)
        bilinear_body<4, 4>(Wc, p * 8);
}

// Handles cnt in (8,16] in one pass.
__global__ void __launch_bounds__(TH, 2)
bilinear_r16(const float* __restrict__ Wc) {
    const int cnt = g_cnt;
    if (cnt <= 8 || cnt > 16) return;
    bilinear_body<8, 2>(Wc, 0);
}

// ============================================================================
// K4a: branch-free streaming write: out[row,:] = heads[row]==0 ? base : 0
//      float4 per thread; grid covers BSROWS*DD/4 elements.
// ============================================================================
__global__ void write_out_kernel(const int* __restrict__ heads,
                                 float* __restrict__ out) {
    const int idx = blockIdx.x * blockDim.x + threadIdx.x;  // < 4096*96
    const int row = idx / (DD / 4);
    const int c4  = idx - row * (DD / 4);
    float4 v = make_float4(0.f, 0.f, 0.f, 0.f);
    if (__ldg(&heads[row]) == 0)
        v = *reinterpret_cast<const float4*>(&g_base[4 * c4]);
    reinterpret_cast<float4*>(out)[idx] = v;
}

// ============================================================================
// K4b: tiny scatter: out[dst_j,o] += (tanh(u[j,o]+bc[o]) - toff[o]) * w[j]
// ============================================================================
__global__ void scatter_kernel(const float* __restrict__ bc,
                               float* __restrict__ out) {
    const int j = blockIdx.x;
    if (j >= g_cnt) return;
    const int o = threadIdx.x;
    float u = g_u[j * DD + o];
    float val = (tanhf(u + bc[o]) - g_toff[o]) * g_w[j];
    atomicAdd(&out[(size_t)g_dst[j] * DD + o], val);
}

// ============================================================================
// launch
// ============================================================================
extern "C" void kernel_launch(void* const* d_in, const int* in_sizes, int n_in,
                              void* d_out, int out_size) {
    const int*   tokens = (const int*)d_in[0];
    // d_in[1] = dep_types: unused (discarded in reference)
    const int*   heads  = (const int*)d_in[2];
    const float* table  = (const float*)d_in[3];
    const float* Wc     = (const float*)d_in[4];
    const float* bc     = (const float*)d_in[5];
    const float* Wr     = (const float*)d_in[6];
    const float* br     = (const float*)d_in[7];
    float* out = (float*)d_out;

    prep_scan_kernel<<<1, SS>>>(heads, bc, Wr, br);
    gather_kernel<<<(MAXR * DD) / 256, 256>>>(tokens, table);
    dim3 g3(NCH, DD);
    bilinear_r8<<<g3, TH>>>(Wc);
    bilinear_r16<<<g3, TH>>>(Wc);
    write_out_kernel<<<(BSROWS * DD / 4) / 256, 256>>>(heads, out);
    scatter_kernel<<<MAXR, DD>>>(bc, out);
}

// round 7
// speedup vs baseline: 2.1487x; 1.2184x over previous
#include <cuda_runtime.h>
#include <cuda_bf16.h>
#include <math.h>

// Problem constants
#define BB 8
#define SS 512
#define DD 384
#define BSROWS (BB * SS)          // 4096
#define MAXR 128                  // cap on relevant s2 rows (expected ~8-12)
#define DCH 96                    // d rows per block
#define NCH (DD / DCH)            // 4
#define TH 384                    // bilinear block size
#define NWARP (TH / 32)           // 12
#define JPMAX 8

typedef unsigned long long ull;

// -------- device scratch (no allocations allowed) --------
__device__ int   g_cnt;
__device__ int   g_src[MAXR];
__device__ int   g_dst[MAXR];
__device__ float g_w[MAXR];
__device__ __align__(16) float g_toff[DD];
__device__ __align__(16) float g_base[DD];
__device__ __align__(16) float g_tok[MAXR * DD];
__device__ __align__(16) float g_dep[MAXR * DD];
__device__ __align__(16) float g_u[MAXR * DD];

#define FMA2(acc, a, b) \
    asm("fma.rn.f32x2 %0, %1, %2, %0;" : "+l"(acc) : "l"(a), "l"(b))
#define DUP(p, f) \
    asm("mov.b64 %0, {%1, %1};" : "=l"(p) : "f"(f))
#define PACK2(p, a, b) \
    asm("mov.b64 %0, {%1, %2};" : "=l"(p) : "f"(a), "f"(b))

// ============================================================================
// K1a: one block, 512 threads. Sequential scan part only.
// ============================================================================
__global__ void prep_scan_kernel(const int* __restrict__ heads,
                                 const float* __restrict__ bc,
                                 const float* __restrict__ Wr,
                                 const float* __restrict__ br) {
    __shared__ float swred[SS];
    __shared__ int cnts[SS];
    const int tid = threadIdx.x;

    // ---- sum of Wr over S ----
    swred[tid] = Wr[tid];
    __syncthreads();
    for (int off = 256; off > 0; off >>= 1) {
        if (tid < off) swred[tid] += swred[tid + off];
        __syncthreads();
    }
    const float sw = swred[0];

    // ---- t_off / base ----
    if (tid < DD) {
        float t = tanhf(bc[tid]);
        g_toff[tid] = t;
        g_base[tid] = t * sw + br[0];
    }

    // ---- deterministic pair list via prefix scan (8 items/thread) ----
    const int base_i = tid * 8;
    int c = 0;
    #pragma unroll
    for (int k = 0; k < 8; k++) {
        int i = base_i + k;
        int h = heads[i];
        int b = i >> 9;
        if (heads[(b << 9) + h] == 0) c++;
    }
    cnts[tid] = c;
    __syncthreads();
    for (int off = 1; off < SS; off <<= 1) {
        int v = (tid >= off) ? cnts[tid - off] : 0;
        __syncthreads();
        cnts[tid] += v;
        __syncthreads();
    }
    const int start = cnts[tid] - c;
    const int total = cnts[SS - 1];
    if (tid == 0) g_cnt = (total > MAXR) ? MAXR : total;

    int pos = start;
    #pragma unroll
    for (int k = 0; k < 8; k++) {
        int i = base_i + k;
        int h = heads[i];
        int b = i >> 9;
        if (heads[(b << 9) + h] == 0) {
            if (pos < MAXR) {
                g_src[pos] = i;
                g_dst[pos] = (b << 9) + h;
                g_w[pos]   = Wr[i & (SS - 1)];
            }
            pos++;
        }
    }
}

// ============================================================================
// K1b: parallel gather + zero. grid 192 x 256 over MAXR*DD elements.
// ============================================================================
__global__ void gather_kernel(const int* __restrict__ tokens,
                              const float* __restrict__ table) {
    const int idx = blockIdx.x * blockDim.x + threadIdx.x;  // < MAXR*DD
    g_u[idx] = 0.f;
    const int j = idx / DD;
    const int d = idx - j * DD;
    float t = 0.f;
    if (j < g_cnt) t = table[(size_t)tokens[g_src[j]] * DD + d];
    g_tok[idx] = t;
    g_dep[idx] = tanhf(t);   // tanh(0)=0 for padded rows
}

// ============================================================================
// Bilinear body: u[jb+j][o] += sum_{d,e} tok[j,d] * Wc[o,d,e] * dep[j,e]
//   JP = j-pairs processed (rows R = 2*JP), EV = e floats per thread.
//   tok j-pairs in smem ({tok[j0,d],tok[j1,d]} packed, row stride JPMAX);
//   W value register-duplicated; 4-deep W prefetch ring.
// ============================================================================
template<int JP, int EV>
__device__ __forceinline__ void bilinear_body(const float* __restrict__ Wc,
                                              int jb,
                                              ull (*tok_s)[JPMAX],
                                              float (*red)[NWARP]) {
    constexpr int R   = 2 * JP;
    constexpr int ETH = DD / EV;        // e-threads per d-phase
    constexpr int DPH = TH / ETH;       // d-phases
    constexpr int KIT = DCH / DPH;      // d iterations per thread

    const int o   = blockIdx.y;
    const int d0  = blockIdx.x * DCH;
    const int tid = threadIdx.x;
    const int et  = tid % ETH;
    const int dph = tid / ETH;

    // fill tok j-pairs
    for (int idx = tid; idx < DCH * JP; idx += TH) {
        int d = idx / JP, q = idx - d * JP;
        float a = g_tok[(jb + 2 * q)     * DD + d0 + d];
        float b = g_tok[(jb + 2 * q + 1) * DD + d0 + d];
        ull p; PACK2(p, a, b);
        tok_s[d][q] = p;
    }
    __syncthreads();

    ull m[JP][EV];
    #pragma unroll
    for (int q = 0; q < JP; q++)
        #pragma unroll
        for (int c = 0; c < EV; c++) m[q][c] = 0ULL;

    const float* Wbase = Wc + ((size_t)o * DD + d0) * DD;

    if constexpr (EV == 4) {
        const float4* __restrict__ Wp = reinterpret_cast<const float4*>(Wbase) + et;
        const int rs = DD / 4;
        float4 wbuf[4];
        #pragma unroll
        for (int p = 0; p < 3; p++)
            wbuf[p] = (p < KIT) ? __ldcs(&Wp[(size_t)(dph + DPH * p) * rs])
                                : make_float4(0.f, 0.f, 0.f, 0.f);
        #pragma unroll
        for (int k = 0; k < KIT; k++) {
            if (k + 3 < KIT)
                wbuf[(k + 3) & 3] = __ldcs(&Wp[(size_t)(dph + DPH * (k + 3)) * rs]);
            float4 w = wbuf[k & 3];
            const int d = dph + DPH * k;
            ull wd0, wd1, wd2, wd3;
            DUP(wd0, w.x); DUP(wd1, w.y); DUP(wd2, w.z); DUP(wd3, w.w);
            #pragma unroll
            for (int q = 0; q < JP; q++) {
                ull tp = tok_s[d][q];
                FMA2(m[q][0], tp, wd0);
                FMA2(m[q][1], tp, wd1);
                FMA2(m[q][2], tp, wd2);
                FMA2(m[q][3], tp, wd3);
            }
        }
    } else {
        const float2* __restrict__ Wp = reinterpret_cast<const float2*>(Wbase) + et;
        const int rs = DD / 2;
        float2 wbuf[4];
        #pragma unroll
        for (int p = 0; p < 3; p++)
            wbuf[p] = (p < KIT) ? __ldcs(&Wp[(size_t)(dph + DPH * p) * rs])
                                : make_float2(0.f, 0.f);
        #pragma unroll
        for (int k = 0; k < KIT; k++) {
            if (k + 3 < KIT)
                wbuf[(k + 3) & 3] = __ldcs(&Wp[(size_t)(dph + DPH * (k + 3)) * rs]);
            float2 w = wbuf[k & 3];
            const int d = dph + DPH * k;
            ull wd0, wd1;
            DUP(wd0, w.x); DUP(wd1, w.y);
            #pragma unroll
            for (int q = 0; q < JP; q++) {
                ull tp = tok_s[d][q];
                FMA2(m[q][0], tp, wd0);
                FMA2(m[q][1], tp, wd1);
            }
        }
    }

    // apply dep at this thread's e-columns, accumulate per row
    float s[R];
    #pragma unroll
    for (int r = 0; r < R; r++) s[r] = 0.f;
    #pragma unroll
    for (int q = 0; q < JP; q++) {
        #pragma unroll
        for (int c = 0; c < EV; c++) {
            float mx, my;
            asm("mov.b64 {%0, %1}, %2;" : "=f"(mx), "=f"(my) : "l"(m[q][c]));
            int e = EV * et + c;
            s[2 * q]     += mx * g_dep[(jb + 2 * q)     * DD + e];
            s[2 * q + 1] += my * g_dep[(jb + 2 * q + 1) * DD + e];
        }
    }

    const int lane = tid & 31;
    const int warp = tid >> 5;
    #pragma unroll
    for (int r = 0; r < R; r++) {
        float v = s[r];
        #pragma unroll
        for (int off = 16; off > 0; off >>= 1)
            v += __shfl_down_sync(0xffffffffu, v, off);
        if (lane == 0) red[r][warp] = v;
    }
    __syncthreads();
    if (tid < R) {
        float acc = 0.f;
        #pragma unroll
        for (int wz = 0; wz < NWARP; wz++) acc += red[tid][wz];
        atomicAdd(&g_u[(jb + tid) * DD + o], acc);
    }
    __syncthreads();
}

// ============================================================================
// K3: single bilinear kernel, exact-JP dispatch on cnt.
// ============================================================================
__global__ void __launch_bounds__(TH, 2)
bilinear_kernel(const float* __restrict__ Wc) {
    const int cnt = g_cnt;
    if (cnt == 0) return;

    __shared__ __align__(16) ull tok_s[DCH][JPMAX];
    __shared__ float red[2 * JPMAX][NWARP];

    if (cnt <= 16) {
        switch ((cnt + 1) >> 1) {
            case 1: bilinear_body<1, 4>(Wc, 0, tok_s, red); break;
            case 2: bilinear_body<2, 4>(Wc, 0, tok_s, red); break;
            case 3: bilinear_body<3, 4>(Wc, 0, tok_s, red); break;
            case 4: bilinear_body<4, 4>(Wc, 0, tok_s, red); break;
            case 5: bilinear_body<5, 2>(Wc, 0, tok_s, red); break;
            case 6: bilinear_body<6, 2>(Wc, 0, tok_s, red); break;
            case 7: bilinear_body<7, 2>(Wc, 0, tok_s, red); break;
            default: bilinear_body<8, 2>(Wc, 0, tok_s, red); break;
        }
    } else {
        const int npass = (cnt + 15) / 16;
        for (int p = 0; p < npass; p++)
            bilinear_body<8, 2>(Wc, 16 * p, tok_s, red);
    }
}

// ============================================================================
// K4 (fused): out[row,:] = heads[row]==0 ? base + scatter-contribs : 0.
//   Destination rows always satisfy heads[dst]==0, so the j-loop only runs
//   on the ~8 masked-in rows (uniform per warp: 96 threads per row).
// ============================================================================
__global__ void write_out_kernel(const int* __restrict__ heads,
                                 const float* __restrict__ bc,
                                 float* __restrict__ out) {
    const int idx = blockIdx.x * blockDim.x + threadIdx.x;  // < 4096*96
    const int row = idx / (DD / 4);
    const int c4  = idx - row * (DD / 4);
    const int o0  = 4 * c4;
    float4 v = make_float4(0.f, 0.f, 0.f, 0.f);
    if (__ldg(&heads[row]) == 0) {
        v = *reinterpret_cast<const float4*>(&g_base[o0]);
        const int cnt = g_cnt;
        for (int j = 0; j < cnt; j++) {
            if (g_dst[j] == row) {
                const float wj = g_w[j];
                const float* up = &g_u[j * DD + o0];
                v.x += (tanhf(up[0] + bc[o0 + 0]) - g_toff[o0 + 0]) * wj;
                v.y += (tanhf(up[1] + bc[o0 + 1]) - g_toff[o0 + 1]) * wj;
                v.z += (tanhf(up[2] + bc[o0 + 2]) - g_toff[o0 + 2]) * wj;
                v.w += (tanhf(up[3] + bc[o0 + 3]) - g_toff[o0 + 3]) * wj;
            }
        }
    }
    reinterpret_cast<float4*>(out)[idx] = v;
}

// ============================================================================
// launch
// ============================================================================
extern "C" void kernel_launch(void* const* d_in, const int* in_sizes, int n_in,
                              void* d_out, int out_size) {
    const int*   tokens = (const int*)d_in[0];
    // d_in[1] = dep_types: unused (discarded in reference)
    const int*   heads  = (const int*)d_in[2];
    const float* table  = (const float*)d_in[3];
    const float* Wc     = (const float*)d_in[4];
    const float* bc     = (const float*)d_in[5];
    const float* Wr     = (const float*)d_in[6];
    const float* br     = (const float*)d_in[7];
    float* out = (float*)d_out;

    prep_scan_kernel<<<1, SS>>>(heads, bc, Wr, br);
    gather_kernel<<<(MAXR * DD) / 256, 256>>>(tokens, table);
    dim3 g3(NCH, DD);
    bilinear_kernel<<<g3, TH>>>(Wc);
    write_out_kernel<<<(BSROWS * DD / 4) / 256, 256>>>(heads, bc, out);
}